// round 1
// baseline (speedup 1.0000x reference)
#include <cuda_runtime.h>
#include <cuda_bf16.h>
#include <math.h>

// ---------------------------------------------------------------------------
// Problem constants
// ---------------------------------------------------------------------------
#define S_LEN   2048
#define HIDDEN  3072
#define NH      32        // query heads
#define NHK     8         // kv heads
#define GQ      4         // H / HK
#define HD      96        // head dim
#define BLK     64        // attention block size
#define NB      32        // S / BLK
#define GH      128       // gate hidden
#define OP      4608      // H*D + 2*HK*D
#define QOFF    0
#define KOFF    3072
#define VOFF    3840

// ---------------------------------------------------------------------------
// Scratch (device globals; no allocation allowed)
// ---------------------------------------------------------------------------
__device__ float g_qkv [S_LEN * OP];          // 37.7 MB  raw qkv (pre-rope)
__device__ float g_q   [S_LEN * NH  * HD];    // 25.2 MB  roped q
__device__ float g_k   [S_LEN * NHK * HD];    //  6.3 MB  roped k
__device__ float g_attn[S_LEN * NH  * HD];    // 25.2 MB  attention output
__device__ float g_qpool[NB * NHK * HD];
__device__ float g_kpool[NB * NHK * 2 * HD];
__device__ float g_qgate[NB * NHK * GH];
__device__ float g_kgate[NB * NHK * GH];
__device__ int   g_maskbuf[NHK * NB * NB];

// ---------------------------------------------------------------------------
// SGEMM: C[M,N] = A[M,K] * B[K,N], all row-major fp32.
// 128x128 tile, BK=8, 256 threads, 8x8 per-thread microtile.
// Requires M%128==0, N%128==0, K%8==0 (true for all our shapes).
// ---------------------------------------------------------------------------
__global__ __launch_bounds__(256, 2)
void sgemm_kernel(const float* __restrict__ A, const float* __restrict__ B,
                  float* __restrict__ C, int M, int N, int K)
{
    __shared__ float As[8][128];   // transposed A tile: As[k][m]
    __shared__ float Bs[8][128];

    const int tid = threadIdx.x;
    const int bn  = blockIdx.x, bm = blockIdx.y;
    const int tx  = tid & 15, ty = tid >> 4;

    const int a_r = tid >> 1, a_c = (tid & 1) * 4;
    const int b_r = tid >> 5, b_c = (tid & 31) * 4;

    const float* Aptr = A + (size_t)(bm * 128 + a_r) * K + a_c;
    const float* Bptr = B + (size_t)b_r * N + bn * 128 + b_c;

    float4 a_reg = *(const float4*)Aptr;
    float4 b_reg = *(const float4*)Bptr;

    float acc[8][8];
#pragma unroll
    for (int i = 0; i < 8; i++)
#pragma unroll
        for (int j = 0; j < 8; j++) acc[i][j] = 0.f;

    const int nk = K >> 3;
    for (int kt = 0; kt < nk; kt++) {
        As[a_c + 0][a_r] = a_reg.x;
        As[a_c + 1][a_r] = a_reg.y;
        As[a_c + 2][a_r] = a_reg.z;
        As[a_c + 3][a_r] = a_reg.w;
        *(float4*)&Bs[b_r][b_c] = b_reg;
        __syncthreads();

        if (kt + 1 < nk) {
            a_reg = *(const float4*)(Aptr + (size_t)(kt + 1) * 8);
            b_reg = *(const float4*)(Bptr + (size_t)(kt + 1) * 8 * N);
        }

#pragma unroll
        for (int k = 0; k < 8; k++) {
            float a[8], b[8];
            *(float4*)(a)     = *(const float4*)&As[k][ty * 4];
            *(float4*)(a + 4) = *(const float4*)&As[k][64 + ty * 4];
            *(float4*)(b)     = *(const float4*)&Bs[k][tx * 4];
            *(float4*)(b + 4) = *(const float4*)&Bs[k][64 + tx * 4];
#pragma unroll
            for (int i = 0; i < 8; i++)
#pragma unroll
                for (int j = 0; j < 8; j++)
                    acc[i][j] += a[i] * b[j];
        }
        __syncthreads();
    }

#pragma unroll
    for (int i = 0; i < 8; i++) {
        int row = bm * 128 + ((i < 4) ? (ty * 4 + i) : (64 + ty * 4 + i - 4));
        float* Crow = C + (size_t)row * N + bn * 128;
        *(float4*)&Crow[tx * 4]      = make_float4(acc[i][0], acc[i][1], acc[i][2], acc[i][3]);
        *(float4*)&Crow[64 + tx * 4] = make_float4(acc[i][4], acc[i][5], acc[i][6], acc[i][7]);
    }
}

// ---------------------------------------------------------------------------
// RoPE: q,k -> g_q, g_k (leaves g_qkv untouched; pooling uses pre-rope values)
// ---------------------------------------------------------------------------
__global__ void rope_kernel(const float* __restrict__ cosb,
                            const float* __restrict__ sinb)
{
    const int total = S_LEN * (NH + NHK) * HD;
    int idx = blockIdx.x * blockDim.x + threadIdx.x;
    if (idx >= total) return;
    int d = idx % HD;
    int h = (idx / HD) % (NH + NHK);
    int s = idx / (HD * (NH + NHK));
    const float* row = g_qkv + (size_t)s * OP;
    float c  = cosb[s * HD + d];
    float sn = sinb[s * HD + d];
    if (h < NH) {
        int base = h * HD;
        float x = row[base + d];
        float r = (d < HD / 2) ? -row[base + d + HD / 2] : row[base + d - HD / 2];
        g_q[(size_t)s * (NH * HD) + h * HD + d] = x * c + r * sn;
    } else {
        int hk = h - NH;
        int base = KOFF + hk * HD;
        float x = row[base + d];
        float r = (d < HD / 2) ? -row[base + d + HD / 2] : row[base + d - HD / 2];
        g_k[(size_t)s * (NHK * HD) + hk * HD + d] = x * c + r * sn;
    }
}

// ---------------------------------------------------------------------------
// Pooling: k mean/max per block, q mean over (G heads x block). Pre-rope.
// grid (NB, NHK), block 96 threads (one per d)
// ---------------------------------------------------------------------------
__global__ void pool_kernel()
{
    int nb = blockIdx.x, hk = blockIdx.y, d = threadIdx.x;
    float ksum = 0.f, kmax = -3.0e38f, qsum = 0.f;
    for (int t = 0; t < BLK; t++) {
        const float* row = g_qkv + (size_t)(nb * BLK + t) * OP;
        float kv = row[KOFF + hk * HD + d];
        ksum += kv;
        kmax = fmaxf(kmax, kv);
#pragma unroll
        for (int g = 0; g < GQ; g++) qsum += row[(hk * GQ + g) * HD + d];
    }
    int bh = nb * NHK + hk;
    g_kpool[bh * (2 * HD) + d]      = ksum * (1.f / BLK);
    g_kpool[bh * (2 * HD) + HD + d] = kmax;
    g_qpool[bh * HD + d]            = qsum * (1.f / (BLK * GQ));
}

// ---------------------------------------------------------------------------
// Gate projections: q_gate = q_pool @ gate_wq, k_gate = k_pool @ gate_wk
// grid (NB, NHK), 128 threads (one per g)
// ---------------------------------------------------------------------------
__global__ void gate_kernel(const float* __restrict__ gate_wq,
                            const float* __restrict__ gate_wk)
{
    int nb = blockIdx.x, hk = blockIdx.y, g = threadIdx.x;
    int bh = nb * NHK + hk;
    float qa = 0.f;
    for (int d = 0; d < HD; d++)
        qa += g_qpool[bh * HD + d] * gate_wq[d * GH + g];
    float ka = 0.f;
    for (int e = 0; e < 2 * HD; e++)
        ka += g_kpool[bh * (2 * HD) + e] * gate_wk[e * GH + g];
    g_qgate[bh * GH + g] = qa;
    g_kgate[bh * GH + g] = ka;
}

// ---------------------------------------------------------------------------
// Block-level gate softmax + threshold -> mask
// grid (NB /*qb*/, NHK), 32 threads (one per kb)
// ---------------------------------------------------------------------------
__global__ void mask_kernel()
{
    int qb = blockIdx.x, hk = blockIdx.y, kb = threadIdx.x;
    float l = -1e30f;
    if (kb <= qb) {
        float dot = 0.f;
        const float* qg = g_qgate + (size_t)(qb * NHK + hk) * GH;
        const float* kg = g_kgate + (size_t)(kb * NHK + hk) * GH;
        for (int g = 0; g < GH; g++) dot += qg[g] * kg[g];
        l = dot * rsqrtf((float)GH);
    }
    float mx = l;
#pragma unroll
    for (int o = 16; o > 0; o >>= 1) mx = fmaxf(mx, __shfl_xor_sync(0xffffffffu, mx, o));
    float e = expf(l - mx);
    float sm = e;
#pragma unroll
    for (int o = 16; o > 0; o >>= 1) sm += __shfl_xor_sync(0xffffffffu, sm, o);
    float p = e / sm;
    int keep = ((p >= 0.03f) && (kb <= qb)) || (kb == qb);
    g_maskbuf[(hk * NB + qb) * NB + kb] = keep;
}

// ---------------------------------------------------------------------------
// Block-sparse flash attention.
// grid (NB /*qb*/, NH /*head*/), 256 threads (16x16), dynamic smem.
// Each thread: 4 score rows x 4 score cols, output tile 4 rows x 6 dims.
// ---------------------------------------------------------------------------
#define ATTN_SMEM ((2 * 96 * 65 + 64 * 65) * 4)

__global__ __launch_bounds__(256)
void attn_kernel()
{
    extern __shared__ float smem[];
    float* Qt = smem;                 // [96][65]  d-major, padded
    float* KV = smem + 96 * 65;       // Kt [96][65]  OR  Vs [64][96]
    float* Pt = smem + 2 * 96 * 65;   // [64][65]  (col-major probs: Pt[c][r])

    const int qb = blockIdx.x, h = blockIdx.y;
    const int hk = h >> 2;
    const int tid = threadIdx.x, tx = tid & 15, ty = tid >> 4;
    const float scale = rsqrtf((float)HD);

    // Load Q tile (roped), pre-scaled, transposed to d-major
    for (int i = tid; i < BLK * HD; i += 256) {
        int r = i / HD, d = i % HD;
        Qt[d * 65 + r] = g_q[(size_t)(qb * BLK + r) * (NH * HD) + h * HD + d] * scale;
    }

    float m[4], l[4], O[4][6];
#pragma unroll
    for (int i = 0; i < 4; i++) {
        m[i] = -1e30f; l[i] = 0.f;
#pragma unroll
        for (int j = 0; j < 6; j++) O[i][j] = 0.f;
    }

    const int* mrow = g_maskbuf + (hk * NB + qb) * NB;

    for (int kb = 0; kb <= qb; kb++) {
        if (!mrow[kb]) continue;            // uniform across the block
        __syncthreads();                    // protect KV reuse

        // Load K tile, transposed to d-major
        for (int i = tid; i < BLK * HD; i += 256) {
            int r = i / HD, d = i % HD;
            KV[d * 65 + r] = g_k[(size_t)(kb * BLK + r) * (NHK * HD) + hk * HD + d];
        }
        __syncthreads();

        // Scores: s[i][j] = sum_d Q[r,d] K[c,d]
        float s[4][4];
#pragma unroll
        for (int i = 0; i < 4; i++)
#pragma unroll
            for (int j = 0; j < 4; j++) s[i][j] = 0.f;

#pragma unroll 4
        for (int d = 0; d < HD; d++) {
            float a[4], b[4];
#pragma unroll
            for (int i = 0; i < 4; i++) a[i] = Qt[d * 65 + ty * 4 + i];
#pragma unroll
            for (int j = 0; j < 4; j++) b[j] = KV[d * 65 + tx * 4 + j];
#pragma unroll
            for (int i = 0; i < 4; i++)
#pragma unroll
                for (int j = 0; j < 4; j++) s[i][j] += a[i] * b[j];
        }

        if (kb == qb) {
#pragma unroll
            for (int i = 0; i < 4; i++)
#pragma unroll
                for (int j = 0; j < 4; j++)
                    if (tx * 4 + j > ty * 4 + i) s[i][j] = -1e30f;
        }

        // Online softmax per row (16 threads share a row: shfl width 16)
#pragma unroll
        for (int i = 0; i < 4; i++) {
            float mr = fmaxf(fmaxf(s[i][0], s[i][1]), fmaxf(s[i][2], s[i][3]));
#pragma unroll
            for (int o = 8; o > 0; o >>= 1)
                mr = fmaxf(mr, __shfl_xor_sync(0xffffffffu, mr, o, 16));
            float nm = fmaxf(m[i], mr);
            float corr = expf(m[i] - nm);
            float rs = 0.f;
#pragma unroll
            for (int j = 0; j < 4; j++) {
                float p = expf(s[i][j] - nm);
                s[i][j] = p;
                rs += p;
            }
#pragma unroll
            for (int o = 8; o > 0; o >>= 1)
                rs += __shfl_xor_sync(0xffffffffu, rs, o, 16);
            l[i] = l[i] * corr + rs;
            m[i] = nm;
#pragma unroll
            for (int j = 0; j < 6; j++) O[i][j] *= corr;
        }

        // Stage probs (transposed: Pt[c][r])
#pragma unroll
        for (int i = 0; i < 4; i++)
#pragma unroll
            for (int j = 0; j < 4; j++)
                Pt[(tx * 4 + j) * 65 + ty * 4 + i] = s[i][j];
        __syncthreads();

        // Load V tile (t-major) into the KV buffer
        for (int i = tid; i < BLK * HD; i += 256) {
            int t = i / HD, d = i % HD;
            KV[t * HD + d] = g_qkv[(size_t)(kb * BLK + t) * OP + VOFF + hk * HD + d];
        }
        __syncthreads();

        // O += P @ V
        for (int t = 0; t < BLK; t++) {
            float pv[4], v[6];
#pragma unroll
            for (int i = 0; i < 4; i++) pv[i] = Pt[t * 65 + ty * 4 + i];
#pragma unroll
            for (int j = 0; j < 6; j++) v[j] = KV[t * HD + tx * 6 + j];
#pragma unroll
            for (int i = 0; i < 4; i++)
#pragma unroll
                for (int j = 0; j < 6; j++) O[i][j] += pv[i] * v[j];
        }
    }

    // Epilogue: normalize and store in [s][h][d] layout (== B,S,H*D)
#pragma unroll
    for (int i = 0; i < 4; i++) {
        float inv = 1.f / l[i];
#pragma unroll
        for (int j = 0; j < 6; j++)
            g_attn[(size_t)(qb * BLK + ty * 4 + i) * (NH * HD) + h * HD + tx * 6 + j]
                = O[i][j] * inv;
    }
}

// ---------------------------------------------------------------------------
// Launch
// ---------------------------------------------------------------------------
extern "C" void kernel_launch(void* const* d_in, const int* in_sizes, int n_in,
                              void* d_out, int out_size)
{
    const float* hs      = (const float*)d_in[0];
    const float* cosb    = (const float*)d_in[1];
    const float* sinb    = (const float*)d_in[2];
    const float* qkv_w   = (const float*)d_in[3];
    const float* o_w     = (const float*)d_in[4];
    const float* gate_wq = (const float*)d_in[5];
    const float* gate_wk = (const float*)d_in[6];
    float* out = (float*)d_out;

    void *p_qkv, *p_attn;
    cudaGetSymbolAddress(&p_qkv, g_qkv);
    cudaGetSymbolAddress(&p_attn, g_attn);

    // 1. QKV projection: [2048,3072] @ [3072,4608]
    sgemm_kernel<<<dim3(OP / 128, S_LEN / 128), 256>>>(
        hs, qkv_w, (float*)p_qkv, S_LEN, OP, HIDDEN);

    // 2. RoPE (q,k)
    {
        int total = S_LEN * (NH + NHK) * HD;
        rope_kernel<<<(total + 255) / 256, 256>>>(cosb, sinb);
    }

    // 3. Pool + gate + mask
    pool_kernel<<<dim3(NB, NHK), HD>>>();
    gate_kernel<<<dim3(NB, NHK), GH>>>(gate_wq, gate_wk);
    mask_kernel<<<dim3(NB, NHK), 32>>>();

    // 4. Block-sparse flash attention
    cudaFuncSetAttribute(attn_kernel,
                         cudaFuncAttributeMaxDynamicSharedMemorySize, ATTN_SMEM);
    attn_kernel<<<dim3(NB, NH), 256, ATTN_SMEM>>>();

    // 5. Output projection: [2048,3072] @ [3072,3072]
    sgemm_kernel<<<dim3(HIDDEN / 128, S_LEN / 128), 256>>>(
        (const float*)p_attn, o_w, out, S_LEN, HIDDEN, HIDDEN);
}

// round 3
// speedup vs baseline: 1.5061x; 1.5061x over previous
#include <cuda_runtime.h>
#include <cuda_bf16.h>
#include <cstdint>
#include <math.h>

// ---------------------------------------------------------------------------
// Problem constants
// ---------------------------------------------------------------------------
#define S_LEN   2048
#define HIDDEN  3072
#define NH      32        // query heads
#define NHK     8         // kv heads
#define GQ      4         // H / HK
#define HD      96        // head dim
#define BLK     64        // attention block size
#define NB      32        // S / BLK
#define GH      128       // gate hidden
#define OP      4608      // H*D + 2*HK*D
#define QOFF    0
#define KOFF    3072
#define VOFF    3840

// ---------------------------------------------------------------------------
// Scratch (device globals; no allocation allowed)
// ---------------------------------------------------------------------------
__device__ float g_qkv [S_LEN * OP];          // raw qkv (pre-rope)
__device__ float g_q   [S_LEN * NH  * HD];    // roped q
__device__ float g_k   [S_LEN * NHK * HD];    // roped k
__device__ float g_attn[S_LEN * NH  * HD];    // attention output
__device__ float g_qpool[NB * NHK * HD];
__device__ float g_kpool[NB * NHK * 2 * HD];
__device__ float g_qgate[NB * NHK * GH];
__device__ float g_kgate[NB * NHK * GH];
__device__ int   g_maskbuf[NHK * NB * NB];

// ---------------------------------------------------------------------------
// TF32 tensor-core GEMM: C[M,N] = A[M,K] * B[K,N], row-major fp32 in/out.
// 128x128 tile, BK=16, 256 threads (8 warps, 2x4 warp grid, 64x32 per warp).
// mma.sync.aligned.m16n8k8.row.col.f32.tf32.tf32.f32
// Requires M%128==0, N%128==0, K%16==0.
// ---------------------------------------------------------------------------
#define PADS 136   // smem row stride (uint32) -> conflict-free fragment loads

__device__ __forceinline__ uint32_t f2tf32(float x) {
    uint32_t y;
    asm("cvt.rna.tf32.f32 %0, %1;" : "=r"(y) : "f"(x));
    return y;
}

__global__ __launch_bounds__(256, 2)
void tf32_gemm(const float* __restrict__ A, const float* __restrict__ B,
               float* __restrict__ C, int M, int N, int K)
{
    __shared__ __align__(16) uint32_t As[2][16][PADS];  // [k][m]
    __shared__ __align__(16) uint32_t Bs[2][16][PADS];  // [k][n]

    const int tid  = threadIdx.x;
    const int bn   = blockIdx.x, bm = blockIdx.y;
    const int warp = tid >> 5,  lane = tid & 31;
    const int wm   = warp >> 2, wn   = warp & 3;
    const int gid  = lane >> 2, tig  = lane & 3;

    // Global load mapping
    const int a_r = tid >> 2;            // 0..63 (and +64)
    const int a_c = (tid & 3) * 4;       // 0,4,8,12
    const int b_r = tid >> 5;            // 0..7  (and +8)
    const int b_c = (tid & 31) * 4;      // 0..124

    const float* Ap = A + (size_t)(bm * 128 + a_r) * K + a_c;
    const float* Bp = B + (size_t)b_r * N + bn * 128 + b_c;

    float4 ra0 = *(const float4*)Ap;
    float4 ra1 = *(const float4*)(Ap + (size_t)64 * K);
    float4 rb0 = *(const float4*)Bp;
    float4 rb1 = *(const float4*)(Bp + (size_t)8 * N);

    // Stage 0 into buffer 0
    {
        As[0][a_c + 0][a_r]      = f2tf32(ra0.x);
        As[0][a_c + 1][a_r]      = f2tf32(ra0.y);
        As[0][a_c + 2][a_r]      = f2tf32(ra0.z);
        As[0][a_c + 3][a_r]      = f2tf32(ra0.w);
        As[0][a_c + 0][a_r + 64] = f2tf32(ra1.x);
        As[0][a_c + 1][a_r + 64] = f2tf32(ra1.y);
        As[0][a_c + 2][a_r + 64] = f2tf32(ra1.z);
        As[0][a_c + 3][a_r + 64] = f2tf32(ra1.w);
        uint4 p0 = make_uint4(f2tf32(rb0.x), f2tf32(rb0.y), f2tf32(rb0.z), f2tf32(rb0.w));
        uint4 p1 = make_uint4(f2tf32(rb1.x), f2tf32(rb1.y), f2tf32(rb1.z), f2tf32(rb1.w));
        *(uint4*)&Bs[0][b_r][b_c]     = p0;
        *(uint4*)&Bs[0][b_r + 8][b_c] = p1;
    }
    __syncthreads();

    float acc[4][4][4];
#pragma unroll
    for (int mt = 0; mt < 4; mt++)
#pragma unroll
        for (int nt = 0; nt < 4; nt++)
#pragma unroll
            for (int r = 0; r < 4; r++) acc[mt][nt][r] = 0.f;

    const int nstage = K >> 4;
    for (int st = 0; st < nstage; st++) {
        const int cur = st & 1;
        const bool more = (st + 1 < nstage);
        if (more) {
            const float* Ap2 = Ap + (size_t)(st + 1) * 16;
            const float* Bp2 = Bp + (size_t)(st + 1) * 16 * N;
            ra0 = *(const float4*)Ap2;
            ra1 = *(const float4*)(Ap2 + (size_t)64 * K);
            rb0 = *(const float4*)Bp2;
            rb1 = *(const float4*)(Bp2 + (size_t)8 * N);
        }

#pragma unroll
        for (int ks = 0; ks < 2; ks++) {
            const int k0 = ks * 8;
            uint32_t af[4][4], bf[4][2];
#pragma unroll
            for (int mt = 0; mt < 4; mt++) {
                const int m0 = wm * 64 + mt * 16;
                af[mt][0] = As[cur][k0 + tig][m0 + gid];
                af[mt][1] = As[cur][k0 + tig][m0 + gid + 8];
                af[mt][2] = As[cur][k0 + tig + 4][m0 + gid];
                af[mt][3] = As[cur][k0 + tig + 4][m0 + gid + 8];
            }
#pragma unroll
            for (int nt = 0; nt < 4; nt++) {
                const int n0 = wn * 32 + nt * 8;
                bf[nt][0] = Bs[cur][k0 + tig][n0 + gid];
                bf[nt][1] = Bs[cur][k0 + tig + 4][n0 + gid];
            }
#pragma unroll
            for (int mt = 0; mt < 4; mt++)
#pragma unroll
                for (int nt = 0; nt < 4; nt++) {
                    asm volatile(
                        "mma.sync.aligned.m16n8k8.row.col.f32.tf32.tf32.f32 "
                        "{%0,%1,%2,%3}, {%4,%5,%6,%7}, {%8,%9}, {%0,%1,%2,%3};"
                        : "+f"(acc[mt][nt][0]), "+f"(acc[mt][nt][1]),
                          "+f"(acc[mt][nt][2]), "+f"(acc[mt][nt][3])
                        : "r"(af[mt][0]), "r"(af[mt][1]), "r"(af[mt][2]), "r"(af[mt][3]),
                          "r"(bf[nt][0]), "r"(bf[nt][1]));
                }
        }

        if (more) {
            const int nxt = cur ^ 1;
            As[nxt][a_c + 0][a_r]      = f2tf32(ra0.x);
            As[nxt][a_c + 1][a_r]      = f2tf32(ra0.y);
            As[nxt][a_c + 2][a_r]      = f2tf32(ra0.z);
            As[nxt][a_c + 3][a_r]      = f2tf32(ra0.w);
            As[nxt][a_c + 0][a_r + 64] = f2tf32(ra1.x);
            As[nxt][a_c + 1][a_r + 64] = f2tf32(ra1.y);
            As[nxt][a_c + 2][a_r + 64] = f2tf32(ra1.z);
            As[nxt][a_c + 3][a_r + 64] = f2tf32(ra1.w);
            uint4 p0 = make_uint4(f2tf32(rb0.x), f2tf32(rb0.y), f2tf32(rb0.z), f2tf32(rb0.w));
            uint4 p1 = make_uint4(f2tf32(rb1.x), f2tf32(rb1.y), f2tf32(rb1.z), f2tf32(rb1.w));
            *(uint4*)&Bs[nxt][b_r][b_c]     = p0;
            *(uint4*)&Bs[nxt][b_r + 8][b_c] = p1;
            __syncthreads();
        }
    }

    // Epilogue
#pragma unroll
    for (int mt = 0; mt < 4; mt++) {
        const int row = bm * 128 + wm * 64 + mt * 16 + gid;
#pragma unroll
        for (int nt = 0; nt < 4; nt++) {
            const int col = bn * 128 + wn * 32 + nt * 8 + tig * 2;
            *(float2*)&C[(size_t)row * N + col] =
                make_float2(acc[mt][nt][0], acc[mt][nt][1]);
            *(float2*)&C[(size_t)(row + 8) * N + col] =
                make_float2(acc[mt][nt][2], acc[mt][nt][3]);
        }
    }
}

// ---------------------------------------------------------------------------
// RoPE: q,k -> g_q, g_k (leaves g_qkv untouched; pooling uses pre-rope values)
// ---------------------------------------------------------------------------
__global__ void rope_kernel(const float* __restrict__ cosb,
                            const float* __restrict__ sinb)
{
    const int total = S_LEN * (NH + NHK) * HD;
    int idx = blockIdx.x * blockDim.x + threadIdx.x;
    if (idx >= total) return;
    int d = idx % HD;
    int h = (idx / HD) % (NH + NHK);
    int s = idx / (HD * (NH + NHK));
    const float* row = g_qkv + (size_t)s * OP;
    float c  = cosb[s * HD + d];
    float sn = sinb[s * HD + d];
    if (h < NH) {
        int base = h * HD;
        float x = row[base + d];
        float r = (d < HD / 2) ? -row[base + d + HD / 2] : row[base + d - HD / 2];
        g_q[(size_t)s * (NH * HD) + h * HD + d] = x * c + r * sn;
    } else {
        int hk = h - NH;
        int base = KOFF + hk * HD;
        float x = row[base + d];
        float r = (d < HD / 2) ? -row[base + d + HD / 2] : row[base + d - HD / 2];
        g_k[(size_t)s * (NHK * HD) + hk * HD + d] = x * c + r * sn;
    }
}

// ---------------------------------------------------------------------------
// Pooling: k mean/max per block, q mean over (G heads x block). Pre-rope.
// grid (NB, NHK), block 96 threads (one per d)
// ---------------------------------------------------------------------------
__global__ void pool_kernel()
{
    int nb = blockIdx.x, hk = blockIdx.y, d = threadIdx.x;
    float ksum = 0.f, kmax = -3.0e38f, qsum = 0.f;
    for (int t = 0; t < BLK; t++) {
        const float* row = g_qkv + (size_t)(nb * BLK + t) * OP;
        float kv = row[KOFF + hk * HD + d];
        ksum += kv;
        kmax = fmaxf(kmax, kv);
#pragma unroll
        for (int g = 0; g < GQ; g++) qsum += row[(hk * GQ + g) * HD + d];
    }
    int bh = nb * NHK + hk;
    g_kpool[bh * (2 * HD) + d]      = ksum * (1.f / BLK);
    g_kpool[bh * (2 * HD) + HD + d] = kmax;
    g_qpool[bh * HD + d]            = qsum * (1.f / (BLK * GQ));
}

// ---------------------------------------------------------------------------
// Gate projections: q_gate = q_pool @ gate_wq, k_gate = k_pool @ gate_wk
// grid (NB, NHK), 128 threads (one per g)
// ---------------------------------------------------------------------------
__global__ void gate_kernel(const float* __restrict__ gate_wq,
                            const float* __restrict__ gate_wk)
{
    int nb = blockIdx.x, hk = blockIdx.y, g = threadIdx.x;
    int bh = nb * NHK + hk;
    float qa = 0.f;
    for (int d = 0; d < HD; d++)
        qa += g_qpool[bh * HD + d] * gate_wq[d * GH + g];
    float ka = 0.f;
    for (int e = 0; e < 2 * HD; e++)
        ka += g_kpool[bh * (2 * HD) + e] * gate_wk[e * GH + g];
    g_qgate[bh * GH + g] = qa;
    g_kgate[bh * GH + g] = ka;
}

// ---------------------------------------------------------------------------
// Block-level gate softmax + threshold -> mask
// grid (NB /*qb*/, NHK), 32 threads (one per kb)
// ---------------------------------------------------------------------------
__global__ void mask_kernel()
{
    int qb = blockIdx.x, hk = blockIdx.y, kb = threadIdx.x;
    float l = -1e30f;
    if (kb <= qb) {
        float dot = 0.f;
        const float* qg = g_qgate + (size_t)(qb * NHK + hk) * GH;
        const float* kg = g_kgate + (size_t)(kb * NHK + hk) * GH;
        for (int g = 0; g < GH; g++) dot += qg[g] * kg[g];
        l = dot * rsqrtf((float)GH);
    }
    float mx = l;
#pragma unroll
    for (int o = 16; o > 0; o >>= 1) mx = fmaxf(mx, __shfl_xor_sync(0xffffffffu, mx, o));
    float e = expf(l - mx);
    float sm = e;
#pragma unroll
    for (int o = 16; o > 0; o >>= 1) sm += __shfl_xor_sync(0xffffffffu, sm, o);
    float p = e / sm;
    int keep = ((p >= 0.03f) && (kb <= qb)) || (kb == qb);
    g_maskbuf[(hk * NB + qb) * NB + kb] = keep;
}

// ---------------------------------------------------------------------------
// Block-sparse flash attention (fp32, shared-memory microtiled).
// grid (NB /*qb*/, NH /*head*/), 256 threads (16x16), dynamic smem.
// ---------------------------------------------------------------------------
#define ATTN_SMEM ((2 * 96 * 65 + 64 * 65) * 4)

__global__ __launch_bounds__(256)
void attn_kernel()
{
    extern __shared__ float smem[];
    float* Qt = smem;                 // [96][65]  d-major, padded
    float* KV = smem + 96 * 65;       // Kt [96][65]  OR  Vs [64][96]
    float* Pt = smem + 2 * 96 * 65;   // [64][65]  (col-major probs: Pt[c][r])

    const int qb = blockIdx.x, h = blockIdx.y;
    const int hk = h >> 2;
    const int tid = threadIdx.x, tx = tid & 15, ty = tid >> 4;
    const float scale = rsqrtf((float)HD);

    for (int i = tid; i < BLK * HD; i += 256) {
        int r = i / HD, d = i % HD;
        Qt[d * 65 + r] = g_q[(size_t)(qb * BLK + r) * (NH * HD) + h * HD + d] * scale;
    }

    float m[4], l[4], O[4][6];
#pragma unroll
    for (int i = 0; i < 4; i++) {
        m[i] = -1e30f; l[i] = 0.f;
#pragma unroll
        for (int j = 0; j < 6; j++) O[i][j] = 0.f;
    }

    const int* mrow = g_maskbuf + (hk * NB + qb) * NB;

    for (int kb = 0; kb <= qb; kb++) {
        if (!mrow[kb]) continue;
        __syncthreads();

        for (int i = tid; i < BLK * HD; i += 256) {
            int r = i / HD, d = i % HD;
            KV[d * 65 + r] = g_k[(size_t)(kb * BLK + r) * (NHK * HD) + hk * HD + d];
        }
        __syncthreads();

        float s[4][4];
#pragma unroll
        for (int i = 0; i < 4; i++)
#pragma unroll
            for (int j = 0; j < 4; j++) s[i][j] = 0.f;

#pragma unroll 4
        for (int d = 0; d < HD; d++) {
            float a[4], b[4];
#pragma unroll
            for (int i = 0; i < 4; i++) a[i] = Qt[d * 65 + ty * 4 + i];
#pragma unroll
            for (int j = 0; j < 4; j++) b[j] = KV[d * 65 + tx * 4 + j];
#pragma unroll
            for (int i = 0; i < 4; i++)
#pragma unroll
                for (int j = 0; j < 4; j++) s[i][j] += a[i] * b[j];
        }

        if (kb == qb) {
#pragma unroll
            for (int i = 0; i < 4; i++)
#pragma unroll
                for (int j = 0; j < 4; j++)
                    if (tx * 4 + j > ty * 4 + i) s[i][j] = -1e30f;
        }

#pragma unroll
        for (int i = 0; i < 4; i++) {
            float mr = fmaxf(fmaxf(s[i][0], s[i][1]), fmaxf(s[i][2], s[i][3]));
#pragma unroll
            for (int o = 8; o > 0; o >>= 1)
                mr = fmaxf(mr, __shfl_xor_sync(0xffffffffu, mr, o, 16));
            float nm = fmaxf(m[i], mr);
            float corr = expf(m[i] - nm);
            float rs = 0.f;
#pragma unroll
            for (int j = 0; j < 4; j++) {
                float p = expf(s[i][j] - nm);
                s[i][j] = p;
                rs += p;
            }
#pragma unroll
            for (int o = 8; o > 0; o >>= 1)
                rs += __shfl_xor_sync(0xffffffffu, rs, o, 16);
            l[i] = l[i] * corr + rs;
            m[i] = nm;
#pragma unroll
            for (int j = 0; j < 6; j++) O[i][j] *= corr;
        }

#pragma unroll
        for (int i = 0; i < 4; i++)
#pragma unroll
            for (int j = 0; j < 4; j++)
                Pt[(tx * 4 + j) * 65 + ty * 4 + i] = s[i][j];
        __syncthreads();

        for (int i = tid; i < BLK * HD; i += 256) {
            int t = i / HD, d = i % HD;
            KV[t * HD + d] = g_qkv[(size_t)(kb * BLK + t) * OP + VOFF + hk * HD + d];
        }
        __syncthreads();

        for (int t = 0; t < BLK; t++) {
            float pv[4], v[6];
#pragma unroll
            for (int i = 0; i < 4; i++) pv[i] = Pt[t * 65 + ty * 4 + i];
#pragma unroll
            for (int j = 0; j < 6; j++) v[j] = KV[t * HD + tx * 6 + j];
#pragma unroll
            for (int i = 0; i < 4; i++)
#pragma unroll
                for (int j = 0; j < 6; j++) O[i][j] += pv[i] * v[j];
        }
    }

#pragma unroll
    for (int i = 0; i < 4; i++) {
        float inv = 1.f / l[i];
#pragma unroll
        for (int j = 0; j < 6; j++)
            g_attn[(size_t)(qb * BLK + ty * 4 + i) * (NH * HD) + h * HD + tx * 6 + j]
                = O[i][j] * inv;
    }
}

// ---------------------------------------------------------------------------
// Launch
// ---------------------------------------------------------------------------
extern "C" void kernel_launch(void* const* d_in, const int* in_sizes, int n_in,
                              void* d_out, int out_size)
{
    const float* hs      = (const float*)d_in[0];
    const float* cosb    = (const float*)d_in[1];
    const float* sinb    = (const float*)d_in[2];
    const float* qkv_w   = (const float*)d_in[3];
    const float* o_w     = (const float*)d_in[4];
    const float* gate_wq = (const float*)d_in[5];
    const float* gate_wk = (const float*)d_in[6];
    float* out = (float*)d_out;

    void *p_qkv, *p_attn;
    cudaGetSymbolAddress(&p_qkv, g_qkv);
    cudaGetSymbolAddress(&p_attn, g_attn);

    // 1. QKV projection: [2048,3072] @ [3072,4608]  (tf32 tensor cores)
    tf32_gemm<<<dim3(OP / 128, S_LEN / 128), 256>>>(
        hs, qkv_w, (float*)p_qkv, S_LEN, OP, HIDDEN);

    // 2. RoPE (q,k)
    {
        int total = S_LEN * (NH + NHK) * HD;
        rope_kernel<<<(total + 255) / 256, 256>>>(cosb, sinb);
    }

    // 3. Pool + gate + mask
    pool_kernel<<<dim3(NB, NHK), HD>>>();
    gate_kernel<<<dim3(NB, NHK), GH>>>(gate_wq, gate_wk);
    mask_kernel<<<dim3(NB, NHK), 32>>>();

    // 4. Block-sparse flash attention
    cudaFuncSetAttribute(attn_kernel,
                         cudaFuncAttributeMaxDynamicSharedMemorySize, ATTN_SMEM);
    attn_kernel<<<dim3(NB, NH), 256, ATTN_SMEM>>>();

    // 5. Output projection: [2048,3072] @ [3072,3072]  (tf32 tensor cores)
    tf32_gemm<<<dim3(HIDDEN / 128, S_LEN / 128), 256>>>(
        (const float*)p_attn, o_w, out, S_LEN, HIDDEN, HIDDEN);
}